// round 17
// baseline (speedup 1.0000x reference)
#include <cuda_runtime.h>
#include <cuda_bf16.h>
#include <math.h>
#include <stdint.h>

#define Bv 64
#define Tv 512
#define Dv 512
#define Uv 1024
#define Gv 4096   // 4*U
#define Kc 1536   // combined K = U + D (W layout; step uses k<1024, xproj k>=1024)
#define NBLK 128

// ---------------------------------------------------------------------------
// Scratch (static device allocations are the sanctioned scratch mechanism)
// ---------------------------------------------------------------------------
__device__ float          g_P[(size_t)Tv * Bv * Gv];     // x-proj + bias, PERMUTED cols
__device__ __nv_bfloat16  g_W_hi[(size_t)Gv * Kc];       // permuted [Wh|Wx] rows, K-major, hi
__device__ __nv_bfloat16  g_W_lo[(size_t)Gv * Kc];       // lo
__device__ __nv_bfloat16  g_xs_hi[(size_t)Tv * Bv * Dv]; // x transposed [t][b][d], hi
__device__ __nv_bfloat16  g_xs_lo[(size_t)Tv * Bv * Dv]; // lo
__device__ __nv_bfloat16  g_h_hi[2][Bv * Uv];            // hidden state hi (dbl buf)
__device__ __nv_bfloat16  g_h_lo[2][Bv * Uv];            // lo
__device__ float          g_c[Bv * Uv];                  // cell state fp32
__device__ int            g_flags[NBLK];                 // grid barrier flags (monotonic)

// ---------------------------------------------------------------------------
// helpers
// ---------------------------------------------------------------------------
__device__ __forceinline__ uint32_t smem_to_u32(const void* p) {
    uint32_t a;
    asm("{ .reg .u64 t; cvta.to.shared.u64 t, %1; cvt.u32.u64 %0, t; }" : "=r"(a) : "l"(p));
    return a;
}
__device__ __forceinline__ void ldsm_x4(uint32_t& r0, uint32_t& r1, uint32_t& r2,
                                        uint32_t& r3, uint32_t addr) {
    asm volatile("ldmatrix.sync.aligned.m8n8.x4.shared.b16 {%0,%1,%2,%3}, [%4];"
                 : "=r"(r0), "=r"(r1), "=r"(r2), "=r"(r3) : "r"(addr));
}
__device__ __forceinline__ void mma_bf16(float* d, uint32_t a0, uint32_t a1,
                                         uint32_t a2, uint32_t a3,
                                         uint32_t b0, uint32_t b1) {
    asm volatile(
        "mma.sync.aligned.m16n8k16.row.col.f32.bf16.bf16.f32 "
        "{%0,%1,%2,%3}, {%4,%5,%6,%7}, {%8,%9}, {%0,%1,%2,%3};"
        : "+f"(d[0]), "+f"(d[1]), "+f"(d[2]), "+f"(d[3])
        : "r"(a0), "r"(a1), "r"(a2), "r"(a3), "r"(b0), "r"(b1));
}
__device__ __forceinline__ void cp16(uint32_t saddr, const void* g) {
    asm volatile("cp.async.cg.shared.global [%0], [%1], 16;" :: "r"(saddr), "l"(g));
}
#define CP_COMMIT() asm volatile("cp.async.commit_group;" ::: "memory")
#define CP_WAIT1()  asm volatile("cp.async.wait_group 1;" ::: "memory")
#define CP_WAIT0()  asm volatile("cp.async.wait_group 0;" ::: "memory")

// swizzled byte offset within a tile with 256B rows (128 bf16 per row)
__device__ __forceinline__ uint32_t swz(int row, int colb) {
    return (uint32_t)(row * 256 + (colb ^ ((row & 7) << 4)));
}

// ---------------------------------------------------------------------------
// init: zero h(buf0) hi/lo, c, barrier flags
// ---------------------------------------------------------------------------
__global__ void init_kernel() {
    int i = blockIdx.x * blockDim.x + threadIdx.x;
    if (i < Bv * Uv) {
        g_h_hi[0][i] = __float2bfloat16(0.0f);
        g_h_lo[0][i] = __float2bfloat16(0.0f);
        g_c[i]       = 0.0f;
    }
    if (i < NBLK) g_flags[i] = 0;
}

// ---------------------------------------------------------------------------
// prep_w: permuted combined split-bf16 weights, K-major rows [4096][1536].
// Row r = blk*32 + g*8 + j  ->  n = g*1024 + blk*8 + j.
// col k: k<1024 -> Wh[k][n];  k>=1024 -> Wx[k-1024][n].
// ---------------------------------------------------------------------------
__global__ __launch_bounds__(256) void prep_w_kernel(
    const float* __restrict__ Wh, const float* __restrict__ Wx)
{
    __shared__ float tile[32][128];
    int tid = threadIdx.x;
    int k0  = blockIdx.x * 128;
    int blk = blockIdx.y;          // 0..127

    int nl = tid & 31;             // g*8 + j
    int g  = nl >> 3;
    int j  = nl & 7;
    int n  = g * Uv + blk * 8 + j;
#pragma unroll 4
    for (int pass = 0; pass < 16; pass++) {
        int k = k0 + (tid >> 5) + pass * 8;
        float w = (k < Uv) ? Wh[(size_t)k * Gv + n]
                           : Wx[(size_t)(k - Uv) * Gv + n];
        tile[nl][(tid >> 5) + pass * 8] = w;
    }
    __syncthreads();

#pragma unroll
    for (int i = 0; i < 2; i++) {
        int idx = tid + i * 256;
        int rl = idx >> 4;
        int q  = idx & 15;
        __nv_bfloat16 hi8[8], lo8[8];
#pragma unroll
        for (int e = 0; e < 8; e++) {
            float w = tile[rl][q * 8 + e];
            __nv_bfloat16 hi = __float2bfloat16(w);
            hi8[e] = hi;
            lo8[e] = __float2bfloat16(w - __bfloat162float(hi));
        }
        size_t o = (size_t)(blk * 32 + rl) * Kc + k0 + q * 8;
        *(uint4*)(g_W_hi + o) = *(uint4*)hi8;
        *(uint4*)(g_W_lo + o) = *(uint4*)lo8;
    }
}

// ---------------------------------------------------------------------------
// prep_x: x[b][t][d] (fp32) -> xs[t][b][d] split bf16.
// ---------------------------------------------------------------------------
__global__ __launch_bounds__(128) void prep_x_kernel(const float* __restrict__ x) {
    int t = blockIdx.x, b = blockIdx.y;
    const float* src = x + ((size_t)b * Tv + t) * Dv;
    size_t dst = ((size_t)t * Bv + b) * Dv;
#pragma unroll
    for (int i = 0; i < 4; i++) {
        int d = threadIdx.x + i * 128;
        float v = src[d];
        __nv_bfloat16 hi = __float2bfloat16(v);
        g_xs_hi[dst + d] = hi;
        g_xs_lo[dst + d] = __float2bfloat16(v - __bfloat162float(hi));
    }
}

// ---------------------------------------------------------------------------
// xproj_mma: P[m][r] = xs[m][:] . W[r][1024:1536]^T + bias (permuted cols),
// 3-term bf16 split. Tile 128m x 64n, K=512 in 4 chunks, 2-stage cp.async.
// ---------------------------------------------------------------------------
#define XKC    128
#define XNCH   4
#define XA_HI  0
#define XA_LO  32768
#define XB_HI  65536
#define XB_LO  81920
#define XST_SZ 98304
#define XPROJ_SMEM (2 * XST_SZ)   // 196608

__global__ __launch_bounds__(256) void xproj_mma(const float* __restrict__ bias)
{
    extern __shared__ __align__(1024) char smem[];
    uint32_t sbase = smem_to_u32(smem);

    const int tid  = threadIdx.x;
    const int wid  = tid >> 5;
    const int lane = tid & 31;
    const int nt   = blockIdx.x;
    const int mt   = blockIdx.y;

    const __nv_bfloat16* A_hi = g_xs_hi + (size_t)mt * 128 * Dv;
    const __nv_bfloat16* A_lo = g_xs_lo + (size_t)mt * 128 * Dv;
    const __nv_bfloat16* B_hi = g_W_hi + (size_t)(nt * 64) * Kc + Uv;
    const __nv_bfloat16* B_lo = g_W_lo + (size_t)(nt * 64) * Kc + Uv;

    const int la_r = tid >> 4;
    const int la_q = tid & 15;

#define ISSUE_X(c)                                                              \
    {                                                                           \
        uint32_t st = sbase + ((c) & 1) * XST_SZ;                               \
        _Pragma("unroll")                                                       \
        for (int i = 0; i < 8; i++) {                                           \
            int r = la_r + i * 16;                                              \
            uint32_t off = swz(r, la_q * 16);                                   \
            cp16(st + XA_HI + off, A_hi + (size_t)r * Dv + (c) * XKC + la_q * 8); \
            cp16(st + XA_LO + off, A_lo + (size_t)r * Dv + (c) * XKC + la_q * 8); \
        }                                                                       \
        _Pragma("unroll")                                                       \
        for (int i = 0; i < 4; i++) {                                           \
            int r = la_r + i * 16;                                              \
            uint32_t off = swz(r, la_q * 16);                                   \
            cp16(st + XB_HI + off, B_hi + (size_t)r * Kc + (c) * XKC + la_q * 8); \
            cp16(st + XB_LO + off, B_lo + (size_t)r * Kc + (c) * XKC + la_q * 8); \
        }                                                                       \
        CP_COMMIT();                                                            \
    }

    const int m0 = (wid >> 1) * 32;
    const int n0 = (wid & 1) * 32;
    const int a_row = m0 + (lane & 15);
    const int a_cb  = (lane >> 4) * 16;
    const int b_row = n0 + ((lane >> 4) << 3) + (lane & 7);
    const int b_cb  = ((lane >> 3) & 1) * 16;

    float d[2][4][4];
#pragma unroll
    for (int i = 0; i < 2; i++)
#pragma unroll
        for (int j = 0; j < 4; j++)
#pragma unroll
            for (int e = 0; e < 4; e++) d[i][j][e] = 0.0f;

    ISSUE_X(0);

    for (int c = 0; c < XNCH; c++) {
        if (c + 1 < XNCH) { ISSUE_X(c + 1); CP_WAIT1(); } else { CP_WAIT0(); }
        __syncthreads();

        uint32_t stb = sbase + (c & 1) * XST_SZ;
#pragma unroll
        for (int ks = 0; ks < XKC / 16; ks++) {
            uint32_t ah[8], al[8], bh[8], bl[8];
            uint32_t ao0 = swz(a_row, ks * 32 + a_cb);
            uint32_t ao1 = swz(a_row + 16, ks * 32 + a_cb);
            uint32_t bo0 = swz(b_row, ks * 32 + b_cb);
            uint32_t bo1 = swz(b_row + 16, ks * 32 + b_cb);
            ldsm_x4(ah[0], ah[1], ah[2], ah[3], stb + XA_HI + ao0);
            ldsm_x4(ah[4], ah[5], ah[6], ah[7], stb + XA_HI + ao1);
            ldsm_x4(al[0], al[1], al[2], al[3], stb + XA_LO + ao0);
            ldsm_x4(al[4], al[5], al[6], al[7], stb + XA_LO + ao1);
            ldsm_x4(bh[0], bh[1], bh[2], bh[3], stb + XB_HI + bo0);
            ldsm_x4(bh[4], bh[5], bh[6], bh[7], stb + XB_HI + bo1);
            ldsm_x4(bl[0], bl[1], bl[2], bl[3], stb + XB_LO + bo0);
            ldsm_x4(bl[4], bl[5], bl[6], bl[7], stb + XB_LO + bo1);

#pragma unroll
            for (int mi = 0; mi < 2; mi++)
#pragma unroll
                for (int ng = 0; ng < 4; ng++)
                    mma_bf16(d[mi][ng], ah[mi*4+0], ah[mi*4+1], ah[mi*4+2], ah[mi*4+3],
                             bh[ng*2], bh[ng*2+1]);
#pragma unroll
            for (int mi = 0; mi < 2; mi++)
#pragma unroll
                for (int ng = 0; ng < 4; ng++)
                    mma_bf16(d[mi][ng], ah[mi*4+0], ah[mi*4+1], ah[mi*4+2], ah[mi*4+3],
                             bl[ng*2], bl[ng*2+1]);
#pragma unroll
            for (int mi = 0; mi < 2; mi++)
#pragma unroll
                for (int ng = 0; ng < 4; ng++)
                    mma_bf16(d[mi][ng], al[mi*4+0], al[mi*4+1], al[mi*4+2], al[mi*4+3],
                             bh[ng*2], bh[ng*2+1]);
        }
        __syncthreads();
    }

    float* ps = (float*)smem;   // 128 x 66
#pragma unroll
    for (int mi = 0; mi < 2; mi++) {
        int row0 = m0 + mi * 16 + (lane >> 2);
        int cbase = (lane & 3) * 2;
#pragma unroll
        for (int ng = 0; ng < 4; ng++) {
            int cc = n0 + ng * 8 + cbase;
            ps[row0 * 66 + cc]           = d[mi][ng][0];
            ps[row0 * 66 + cc + 1]       = d[mi][ng][1];
            ps[(row0 + 8) * 66 + cc]     = d[mi][ng][2];
            ps[(row0 + 8) * 66 + cc + 1] = d[mi][ng][3];
        }
    }
    __syncthreads();

#pragma unroll
    for (int i = 0; i < 8; i++) {
        int idx = tid + i * 256;
        int row = idx >> 4;
        int c4  = (idx & 15) * 4;
        float4 v;
        float* pp = &ps[row * 66 + c4];
        v.x = pp[0]; v.y = pp[1]; v.z = pp[2]; v.w = pp[3];
        float* ve = &v.x;
#pragma unroll
        for (int e = 0; e < 4; e++) {
            int r = nt * 64 + c4 + e;
            int orig = (((r & 31) >> 3) << 10) + ((r >> 5) << 3) + (r & 7);
            ve[e] += bias[orig];
        }
        size_t mrow = (size_t)mt * 128 + row;
        *(float4*)(g_P + mrow * Gv + nt * 64 + c4) = v;
    }
}

// ---------------------------------------------------------------------------
// Persistent LSTM recurrence. 128 CTAs x 256 threads, 1 CTA/SM.
// W slice resident in SMEM (131072 B). h streamed in 8 chunks of 128 K,
// 2-stage cp.async (wait -> sync -> issue: race-free, depth-1 overlap).
// Warp layout: 8 warps = 2 m-halves (32 rows) x 4 k-groups (2 k16 each);
// warp tile m32 x n32 -> 8 LDSM feed 24 MMAs per k16.
// Flag-array grid barrier (no serialized atomics). P/c prefetched at step top.
// SMEM: W 131072 | h 2x32768 = 196608 B. gs partials overlay h region.
// ---------------------------------------------------------------------------
#define KC      128
#define NCH     8            // 1024 / 128
#define W_SM    0            // W: part*65536 + chunk*8192 + swz(row32, colb)
#define H_SM    131072       // h: buf*32768 + part*16384 + swz(row64, colb)
#define PERS_SMEM 196608

__global__ __launch_bounds__(256) void lstm_persist(float* __restrict__ out)
{
    extern __shared__ __align__(1024) char smem[];
    uint32_t sbase = smem_to_u32(smem);

    const int tid  = threadIdx.x;
    const int wid  = tid >> 5;
    const int lane = tid & 31;
    const int blk  = blockIdx.x;

    const __nv_bfloat16* Wg_hi = g_W_hi + (size_t)blk * 32 * Kc;
    const __nv_bfloat16* Wg_lo = g_W_lo + (size_t)blk * 32 * Kc;

    // ---- one-time W preload into swizzled SMEM ----
    for (int i = tid; i < 4096; i += 256) {
        int r = i >> 7;            // 0..31
        int q = i & 127;           // 16B unit within 1024 K
        int c = q >> 4;            // chunk
        int qq = q & 15;
        uint32_t off = W_SM + c * 8192 + swz(r, qq * 16);
        cp16(sbase + off,         Wg_hi + (size_t)r * Kc + q * 8);
        cp16(sbase + 65536 + off, Wg_lo + (size_t)r * Kc + q * 8);
    }
    CP_COMMIT(); CP_WAIT0();
    __syncthreads();

    const int la_r = tid >> 4;     // 0..15
    const int la_q = tid & 15;

#define ISSUE_H(Hhi, Hlo, c)                                                     \
    {                                                                            \
        uint32_t st = sbase + H_SM + ((c) & 1) * 32768;                          \
        _Pragma("unroll")                                                        \
        for (int i = 0; i < 4; i++) {                                            \
            int r = la_r + i * 16;                                               \
            uint32_t off = swz(r, la_q * 16);                                    \
            cp16(st + off,         (Hhi) + (size_t)r * Uv + (c) * KC + la_q * 8);\
            cp16(st + 16384 + off, (Hlo) + (size_t)r * Uv + (c) * KC + la_q * 8);\
        }                                                                        \
        CP_COMMIT();                                                             \
    }

    // warp mapping: m-half x k-group
    const int mhalf = wid & 1;
    const int kgrp  = wid >> 1;                 // 0..3
    const int m0    = mhalf * 32;
    const int a_row = m0 + (lane & 15);
    const int a_cb  = (lane >> 4) * 16;
    const int b_row = ((lane >> 4) << 3) + (lane & 7);   // 0..15 within W tile
    const int b_cb  = ((lane >> 3) & 1) * 16;

    // pointwise coords (2 pairs per thread)
    int pw_b[2], pw_j[2];
#pragma unroll
    for (int i = 0; i < 2; i++) {
        int p = tid + i * 256;
        pw_b[i] = p >> 3;
        pw_j[i] = p & 7;
    }

    for (int t = 0; t < Tv; t++) {
        const __nv_bfloat16* H_hi = g_h_hi[t & 1];
        const __nv_bfloat16* H_lo = g_h_lo[t & 1];

        // prefetch P (8 floats) and c-state (2 floats); latency hides under GEMM
        float pf[2][4], cpre[2];
#pragma unroll
        for (int i = 0; i < 2; i++) {
            const float* Pb = g_P + ((size_t)t * Bv + pw_b[i]) * Gv + blk * 32;
#pragma unroll
            for (int g = 0; g < 4; g++) pf[i][g] = Pb[g * 8 + pw_j[i]];
            cpre[i] = g_c[pw_b[i] * Uv + blk * 8 + pw_j[i]];
        }

        float d[2][4][4];
#pragma unroll
        for (int mi = 0; mi < 2; mi++)
#pragma unroll
            for (int ng = 0; ng < 4; ng++)
#pragma unroll
                for (int e = 0; e < 4; e++) d[mi][ng][e] = 0.0f;

        ISSUE_H(H_hi, H_lo, 0);

        for (int c = 0; c < NCH; c++) {
            CP_WAIT0();
            __syncthreads();
            if (c + 1 < NCH) ISSUE_H(H_hi, H_lo, c + 1);

            uint32_t hb  = sbase + H_SM + (c & 1) * 32768;
            uint32_t wb  = sbase + W_SM + c * 8192;
            uint32_t wbl = wb + 65536;
#pragma unroll
            for (int s = 0; s < 2; s++) {
                int k16 = kgrp * 2 + s;
                uint32_t ah[8], al[8], bh[8], bl[8];
                uint32_t ao0 = swz(a_row,      k16 * 32 + a_cb);
                uint32_t ao1 = swz(a_row + 16, k16 * 32 + a_cb);
                uint32_t bo0 = swz(b_row,      k16 * 32 + b_cb);
                uint32_t bo1 = swz(b_row + 16, k16 * 32 + b_cb);
                ldsm_x4(ah[0], ah[1], ah[2], ah[3], hb + ao0);
                ldsm_x4(ah[4], ah[5], ah[6], ah[7], hb + ao1);
                ldsm_x4(al[0], al[1], al[2], al[3], hb + 16384 + ao0);
                ldsm_x4(al[4], al[5], al[6], al[7], hb + 16384 + ao1);
                ldsm_x4(bh[0], bh[1], bh[2], bh[3], wb + bo0);
                ldsm_x4(bh[4], bh[5], bh[6], bh[7], wb + bo1);
                ldsm_x4(bl[0], bl[1], bl[2], bl[3], wbl + bo0);
                ldsm_x4(bl[4], bl[5], bl[6], bl[7], wbl + bo1);

#pragma unroll
                for (int mi = 0; mi < 2; mi++)
#pragma unroll
                    for (int ng = 0; ng < 4; ng++)
                        mma_bf16(d[mi][ng], ah[mi*4+0], ah[mi*4+1], ah[mi*4+2], ah[mi*4+3],
                                 bh[ng*2], bh[ng*2+1]);
#pragma unroll
                for (int mi = 0; mi < 2; mi++)
#pragma unroll
                    for (int ng = 0; ng < 4; ng++)
                        mma_bf16(d[mi][ng], ah[mi*4+0], ah[mi*4+1], ah[mi*4+2], ah[mi*4+3],
                                 bl[ng*2], bl[ng*2+1]);
#pragma unroll
                for (int mi = 0; mi < 2; mi++)
#pragma unroll
                    for (int ng = 0; ng < 4; ng++)
                        mma_bf16(d[mi][ng], al[mi*4+0], al[mi*4+1], al[mi*4+2], al[mi*4+3],
                                 bh[ng*2], bh[ng*2+1]);
            }
        }
        __syncthreads();   // all warps done reading h stages before gs overlay

        // park 4 k-group partials in SMEM (overlay h region): gs[kgrp][64][33]
        {
            float* gsk = (float*)(smem + H_SM) + kgrp * 2112;   // 64*33
#pragma unroll
            for (int mi = 0; mi < 2; mi++) {
                int row0 = m0 + mi * 16 + (lane >> 2);
                int cb = (lane & 3) * 2;
#pragma unroll
                for (int ng = 0; ng < 4; ng++) {
                    int cc = ng * 8 + cb;
                    gsk[row0 * 33 + cc]           = d[mi][ng][0];
                    gsk[row0 * 33 + cc + 1]       = d[mi][ng][1];
                    gsk[(row0 + 8) * 33 + cc]     = d[mi][ng][2];
                    gsk[(row0 + 8) * 33 + cc + 1] = d[mi][ng][3];
                }
            }
        }
        __syncthreads();

        // fused LSTM pointwise: 64 batches x 8 units = 512 pairs, 2/thread
        __nv_bfloat16* nh_hi = g_h_hi[(t + 1) & 1];
        __nv_bfloat16* nh_lo = g_h_lo[(t + 1) & 1];
        const float* gs0 = (float*)(smem + H_SM);
#pragma unroll
        for (int i = 0; i < 2; i++) {
            int b = pw_b[i];
            int j = pw_j[i];
            int u = blk * 8 + j;

            float xi = pf[i][0], xf = pf[i][1], xg = pf[i][2], xo = pf[i][3];
#pragma unroll
            for (int kg = 0; kg < 4; kg++) {
                const float* g = gs0 + kg * 2112 + b * 33;
                xi += g[0 * 8 + j];
                xf += g[1 * 8 + j];
                xg += g[2 * 8 + j];
                xo += g[3 * 8 + j];
            }

            float ig = 1.0f / (1.0f + expf(-xi));
            float fg = 1.0f / (1.0f + expf(-xf));
            float gg = tanhf(xg);
            float og = 1.0f / (1.0f + expf(-xo));

            int idx = b * Uv + u;
            float cc = fg * cpre[i] + ig * gg;
            g_c[idx] = cc;
            float h = og * tanhf(cc);

            out[((size_t)b * Tv + t) * Uv + u] = h;
            __nv_bfloat16 hh = __float2bfloat16(h);
            nh_hi[idx] = hh;
            nh_lo[idx] = __float2bfloat16(h - __bfloat162float(hh));
        }

        // flag-array grid barrier (skip after final step)
        __syncthreads();
        if (t + 1 < Tv) {
            if (tid == 0) {
                __threadfence();
                asm volatile("st.release.gpu.global.b32 [%0], %1;"
                             :: "l"(&g_flags[blk]), "r"(t + 1) : "memory");
            }
            if (tid < NBLK) {
                int v;
                do {
                    asm volatile("ld.acquire.gpu.global.b32 %0, [%1];"
                                 : "=r"(v) : "l"(&g_flags[tid]));
                } while (v < t + 1);
            }
            __syncthreads();
        }
    }
}

// ---------------------------------------------------------------------------
// Launch: init -> prep_w -> prep_x -> xproj_mma -> ONE persistent kernel
// ---------------------------------------------------------------------------
extern "C" void kernel_launch(void* const* d_in, const int* in_sizes, int n_in,
                              void* d_out, int out_size)
{
    const float* x    = (const float*)d_in[0];   // [64, 512, 512]
    const float* Wx   = (const float*)d_in[1];   // [512, 4096]
    const float* Wh   = (const float*)d_in[2];   // [1024, 4096]
    const float* bias = (const float*)d_in[3];   // [4096]
    float* out = (float*)d_out;                  // [64, 512, 1024]

    static int configured = 0;
    if (!configured) {
        cudaFuncSetAttribute(lstm_persist,
                             cudaFuncAttributeMaxDynamicSharedMemorySize, PERS_SMEM);
        cudaFuncSetAttribute(xproj_mma,
                             cudaFuncAttributeMaxDynamicSharedMemorySize, XPROJ_SMEM);
        configured = 1;
    }

    init_kernel<<<(Bv * Uv + 255) / 256, 256>>>();

    dim3 wgrid(Kc / 128, Gv / 32);
    prep_w_kernel<<<wgrid, 256>>>(Wh, Wx);

    dim3 xgrid(Tv, Bv);
    prep_x_kernel<<<xgrid, 128>>>(x);

    dim3 pgrid(Gv / 64, (Tv * Bv) / 128);
    xproj_mma<<<pgrid, 256, XPROJ_SMEM>>>(bias);

    lstm_persist<<<NBLK, 256, PERS_SMEM>>>(out);
}